// round 3
// baseline (speedup 1.0000x reference)
#include <cuda_runtime.h>

#define D 128
#define VCAP 100000
#define CAP 128          // adjacency slots per node
#define GB_ROWS 96       // GEMM rows per tile
#define NTHR 384         // 12 warps
#define WS 256           // wsT row stride (row-contiguous reads -> no pad needed)

// packed f32x2 FMA: acc = a*b + acc (lanewise on 2 packed fp32)
#define FMA2(acc, a, b) \
    asm("fma.rn.f32x2 %0, %1, %2, %0;" : "+l"(acc) : "l"(a), "l"(b))

__device__ __forceinline__ unsigned long long splat2(float v) {
    unsigned long long r;
    unsigned int u = __float_as_uint(v);
    asm("mov.b64 %0, {%1, %1};" : "=l"(r) : "r"(u));
    return r;
}
__device__ __forceinline__ unsigned long long pack2(float lo, float hi) {
    unsigned long long r;
    asm("mov.b64 %0, {%1, %2};" : "=l"(r) : "r"(__float_as_uint(lo)), "r"(__float_as_uint(hi)));
    return r;
}
__device__ __forceinline__ void unpack2(unsigned long long p, float& lo, float& hi) {
    asm("mov.b64 {%0, %1}, %2;" : "=f"(lo), "=f"(hi) : "l"(p));
}

__device__ __forceinline__ unsigned int smem_u32(const void* p) {
    return (unsigned int)__cvta_generic_to_shared(p);
}
__device__ __forceinline__ void cp_async16(unsigned int dst, const void* src, int src_bytes) {
    asm volatile("cp.async.cg.shared.global [%0], [%1], 16, %2;"
                 :: "r"(dst), "l"(src), "r"(src_bytes));
}
__device__ __forceinline__ void cp_commit() { asm volatile("cp.async.commit_group;"); }
__device__ __forceinline__ void cp_wait_all() { asm volatile("cp.async.wait_group 0;"); }

// ---------------- scratch (static device globals; no allocs) ----------------
__device__ float g_h0[(size_t)VCAP * D];
__device__ float g_h1[(size_t)VCAP * D];
__device__ float g_y [(size_t)VCAP * D];
__device__ int   g_adj[(size_t)VCAP * CAP];
__device__ int   g_cnt[VCAP];
__device__ float g_dinv[VCAP];
__device__ float g_stats[3 * 2 * D];

// ---------------- prologue kernels ----------------
__global__ void zero_kernel(int V) {
    int i = blockIdx.x * blockDim.x + threadIdx.x;
    if (i < V) g_cnt[i] = 0;
    if (i < 3 * 2 * D) g_stats[i] = 0.0f;
}

__global__ void build_adj(const int* __restrict__ edges, int E) {
    int e = blockIdx.x * blockDim.x + threadIdx.x;
    if (e >= E) return;
    int a = edges[2 * e];
    int b = edges[2 * e + 1];
    int pa = atomicAdd(&g_cnt[a], 1);
    if (pa < CAP) g_adj[(size_t)a * CAP + pa] = b;
    int pb = atomicAdd(&g_cnt[b], 1);
    if (pb < CAP) g_adj[(size_t)b * CAP + pb] = a;
}

__global__ void dinv_kernel(int V) {
    int i = blockIdx.x * blockDim.x + threadIdx.x;
    if (i < V) g_dinv[i] = 1.0f / (1.0f + (float)g_cnt[i]);
}

// ---------------- dual GEMM (FFMA2, cp.async double-buffered, b-prefetch) ----------------
__global__ void __launch_bounds__(NTHR, 1) gemm_dual(
    const float* __restrict__ xext, int layer,
    const float* __restrict__ W0, const float* __restrict__ b0,
    const float* __restrict__ W1, const float* __restrict__ b1,
    const float* __restrict__ gammaPrev, const float* __restrict__ betaPrev,
    int V, float invV)
{
    extern __shared__ float smem[];
    float* wsT = smem;                        // [128][256]
    float* xs0 = smem + 128 * WS;             // [96][128] buffer 0
    float* xs1 = xs0 + GB_ROWS * D;           // [96][128] buffer 1
    __shared__ float s_sc[D];
    __shared__ float s_sh[D];

    const float* x = (layer == 0) ? xext : g_y;
    const bool doNorm = (layer != 0);

    int tid = threadIdx.x;

    if (doNorm && tid < D) {
        const float* st = g_stats + (layer - 1) * 2 * D;
        float mu  = st[tid] * invV;
        float var = st[D + tid] * invV - mu * mu;
        float rs  = rsqrtf(var + 1e-5f);
        float sc  = gammaPrev[tid] * rs;
        s_sc[tid] = sc;
        s_sh[tid] = betaPrev[tid] - mu * sc;
    }

    // --- W0||W1 transposed into SMEM once per block ---
    {
        int kk4 = (tid & 7) * 4;
        int c0  = tid >> 3;          // 0..47
        for (int col = c0; col < 256; col += 48) {
            const float* Wp = (col < D) ? (W0 + (size_t)col * D)
                                        : (W1 + (size_t)(col - D) * D);
            #pragma unroll
            for (int kb = 0; kb < 4; kb++) {
                int kk = kb * 32 + kk4;
                float4 g = *(const float4*)(Wp + kk);
                wsT[(kk + 0) * WS + col] = g.x;
                wsT[(kk + 1) * WS + col] = g.y;
                wsT[(kk + 2) * WS + col] = g.z;
                wsT[(kk + 3) * WS + col] = g.w;
            }
        }
    }

    int wid  = tid >> 5;
    int lane = tid & 31;
    int ry8  = wid * 8;
    int cx4  = lane * 4;

    // per-thread cp.async source/dest coords for tile loads (8 chunks)
    // chunk it: element f = tid + it*NTHR ; row = f>>5 ; col4 = (f&31)*4
    int numTiles = (V + GB_ROWS - 1) / GB_ROWS;
    int t0 = blockIdx.x;

    // prologue: stage tile t0 into xs0
    if (t0 < numTiles) {
        int r0 = t0 * GB_ROWS;
        #pragma unroll
        for (int it = 0; it < 8; it++) {
            int f  = tid + it * NTHR;
            int r  = f >> 5;
            int c4 = (f & 31) * 4;
            int row = r0 + r;
            const float* src = x + (size_t)(row < V ? row : 0) * D + c4;
            cp_async16(smem_u32(xs0 + r * D + c4), src, (row < V) ? 16 : 0);
        }
    }
    cp_commit();
    cp_wait_all();
    __syncthreads();   // W ready + tile0 ready

    float4 bq0 = *(const float4*)(b0 + cx4);
    float4 bq1 = *(const float4*)(b1 + cx4);
    unsigned long long bias0[2] = { pack2(bq0.x, bq0.y), pack2(bq0.z, bq0.w) };
    unsigned long long bias1[2] = { pack2(bq1.x, bq1.y), pack2(bq1.z, bq1.w) };

    int pbuf = 0;
    for (int t = t0; t < numTiles; t += gridDim.x) {
        float* xs  = pbuf ? xs1 : xs0;
        float* xsn = pbuf ? xs0 : xs1;
        int r0 = t * GB_ROWS;

        // stage next tile for THIS block into the other buffer
        int tn = t + gridDim.x;
        if (tn < numTiles) {
            int rn0 = tn * GB_ROWS;
            #pragma unroll
            for (int it = 0; it < 8; it++) {
                int f  = tid + it * NTHR;
                int r  = f >> 5;
                int c4 = (f & 31) * 4;
                int row = rn0 + r;
                const float* src = x + (size_t)(row < V ? row : 0) * D + c4;
                cp_async16(smem_u32(xsn + r * D + c4), src, (row < V) ? 16 : 0);
            }
        }
        cp_commit();

        unsigned long long acc0[8][2];
        unsigned long long acc1[8][2];
        #pragma unroll
        for (int i = 0; i < 8; i++) {
            acc0[i][0] = bias0[0]; acc0[i][1] = bias0[1];
            acc1[i][0] = bias1[0]; acc1[i][1] = bias1[1];
        }

        // BN+ReLU on the fly (layers 1,2) applied to the a-operand
        const float* wp = wsT + cx4;
        ulonglong2 b0c = *(const ulonglong2*)(wp);
        ulonglong2 b1c = *(const ulonglong2*)(wp + 128);

        for (int kq = 0; kq < D / 4; kq++) {
            float4 a4[8];
            #pragma unroll
            for (int i = 0; i < 8; i++) {
                float4 a = *(const float4*)(xs + (ry8 + i) * D + kq * 4);
                if (doNorm) {
                    int c4 = kq * 4;
                    a.x = fmaxf(fmaf(a.x, s_sc[c4 + 0], s_sh[c4 + 0]), 0.f);
                    a.y = fmaxf(fmaf(a.y, s_sc[c4 + 1], s_sh[c4 + 1]), 0.f);
                    a.z = fmaxf(fmaf(a.z, s_sc[c4 + 2], s_sh[c4 + 2]), 0.f);
                    a.w = fmaxf(fmaf(a.w, s_sc[c4 + 3], s_sh[c4 + 3]), 0.f);
                }
                a4[i] = a;
            }

            #pragma unroll
            for (int kk = 0; kk < 4; kk++) {
                int kn = kq * 4 + kk + 1;
                ulonglong2 b0n, b1n;
                if (kn < D) {
                    const float* wn = wsT + kn * WS + cx4;
                    b0n = *(const ulonglong2*)(wn);
                    b1n = *(const ulonglong2*)(wn + 128);
                }
                #pragma unroll
                for (int i = 0; i < 8; i++) {
                    float av = (kk == 0) ? a4[i].x : (kk == 1) ? a4[i].y
                             : (kk == 2) ? a4[i].z : a4[i].w;
                    unsigned long long ap = splat2(av);
                    FMA2(acc0[i][0], ap, b0c.x);
                    FMA2(acc0[i][1], ap, b0c.y);
                    FMA2(acc1[i][0], ap, b1c.x);
                    FMA2(acc1[i][1], ap, b1c.y);
                }
                if (kn < D) { b0c = b0n; b1c = b1n; }
            }
        }

        #pragma unroll
        for (int i = 0; i < 8; i++) {
            int row = r0 + ry8 + i;
            if (row < V) {
                float4 o0, o1;
                unpack2(acc0[i][0], o0.x, o0.y);
                unpack2(acc0[i][1], o0.z, o0.w);
                unpack2(acc1[i][0], o1.x, o1.y);
                unpack2(acc1[i][1], o1.z, o1.w);
                *(float4*)(g_h0 + (size_t)row * D + cx4) = o0;
                *(float4*)(g_h1 + (size_t)row * D + cx4) = o1;
            }
        }

        cp_wait_all();        // next tile staged
        __syncthreads();      // everyone done reading xs + next buffer ready
        pbuf ^= 1;
    }
}

// ---------------- aggregation + BN stats ----------------
__global__ void __launch_bounds__(256) agg_kernel(float* __restrict__ stats, int V)
{
    __shared__ float s_sum[D];
    __shared__ float s_sq[D];

    int tid  = threadIdx.x;
    int wid  = tid >> 5;
    int lane = tid & 31;
    int c0   = lane * 4;

    if (tid < D) { s_sum[tid] = 0.f; s_sq[tid] = 0.f; }
    __syncthreads();

    float4 psum = make_float4(0.f, 0.f, 0.f, 0.f);
    float4 psq  = make_float4(0.f, 0.f, 0.f, 0.f);

    int warpStride = gridDim.x * 8;
    for (int v = blockIdx.x * 8 + wid; v < V; v += warpStride) {
        float4 acc = *(const float4*)(g_h0 + (size_t)v * D + c0);
        int n = g_cnt[v];
        const int* ap = g_adj + (size_t)v * CAP;
        int e = 0;
        for (; e + 3 < n; e += 4) {
            int u0 = ap[e], u1 = ap[e + 1], u2 = ap[e + 2], u3 = ap[e + 3];
            float4 t0 = __ldg((const float4*)(g_h1 + (size_t)u0 * D + c0));
            float4 t1 = __ldg((const float4*)(g_h1 + (size_t)u1 * D + c0));
            float4 t2 = __ldg((const float4*)(g_h1 + (size_t)u2 * D + c0));
            float4 t3 = __ldg((const float4*)(g_h1 + (size_t)u3 * D + c0));
            acc.x += (t0.x + t1.x) + (t2.x + t3.x);
            acc.y += (t0.y + t1.y) + (t2.y + t3.y);
            acc.z += (t0.z + t1.z) + (t2.z + t3.z);
            acc.w += (t0.w + t1.w) + (t2.w + t3.w);
        }
        for (; e < n; e++) {
            int u = ap[e];
            float4 t = __ldg((const float4*)(g_h1 + (size_t)u * D + c0));
            acc.x += t.x; acc.y += t.y; acc.z += t.z; acc.w += t.w;
        }
        float dv = g_dinv[v];
        acc.x *= dv; acc.y *= dv; acc.z *= dv; acc.w *= dv;
        *(float4*)(g_y + (size_t)v * D + c0) = acc;

        psum.x += acc.x; psum.y += acc.y; psum.z += acc.z; psum.w += acc.w;
        psq.x  += acc.x * acc.x; psq.y += acc.y * acc.y;
        psq.z  += acc.z * acc.z; psq.w += acc.w * acc.w;
    }

    atomicAdd(&s_sum[c0 + 0], psum.x);
    atomicAdd(&s_sum[c0 + 1], psum.y);
    atomicAdd(&s_sum[c0 + 2], psum.z);
    atomicAdd(&s_sum[c0 + 3], psum.w);
    atomicAdd(&s_sq[c0 + 0],  psq.x);
    atomicAdd(&s_sq[c0 + 1],  psq.y);
    atomicAdd(&s_sq[c0 + 2],  psq.z);
    atomicAdd(&s_sq[c0 + 3],  psq.w);
    __syncthreads();

    if (tid < D) {
        atomicAdd(&stats[tid],     s_sum[tid]);
        atomicAdd(&stats[D + tid], s_sq[tid]);
    }
}

// ---------------- final BN + ReLU + residual -> out ----------------
__global__ void __launch_bounds__(256) norm_final(
    const float* __restrict__ stats,
    const float* __restrict__ gamma, const float* __restrict__ beta,
    const float* __restrict__ res,
    float* __restrict__ out, int V, float invV)
{
    __shared__ float s_scale[D];
    __shared__ float s_shift[D];

    int tid = threadIdx.x;
    if (tid < D) {
        float mu  = stats[tid] * invV;
        float var = stats[D + tid] * invV - mu * mu;
        float rs  = rsqrtf(var + 1e-5f);
        float sc  = gamma[tid] * rs;
        s_scale[tid] = sc;
        s_shift[tid] = beta[tid] - mu * sc;
    }
    __syncthreads();

    int total = V * (D / 4);
    for (int f = blockIdx.x * blockDim.x + tid; f < total; f += gridDim.x * blockDim.x) {
        int c = (f & 31) * 4;
        float4 t = *(const float4*)(g_y + (size_t)f * 4);
        float4 r = *(const float4*)(res + (size_t)f * 4);
        float4 o;
        o.x = fmaxf(fmaf(t.x, s_scale[c + 0], s_shift[c + 0]) + r.x, 0.f);
        o.y = fmaxf(fmaf(t.y, s_scale[c + 1], s_shift[c + 1]) + r.y, 0.f);
        o.z = fmaxf(fmaf(t.z, s_scale[c + 2], s_shift[c + 2]) + r.z, 0.f);
        o.w = fmaxf(fmaf(t.w, s_scale[c + 3], s_shift[c + 3]) + r.w, 0.f);
        *(float4*)(out + (size_t)f * 4) = o;
    }
}

// ---------------- launch ----------------
extern "C" void kernel_launch(void* const* d_in, const int* in_sizes, int n_in,
                              void* d_out, int out_size)
{
    const float* features = (const float*)d_in[0];
    const int*   edges    = (const int*)  d_in[1];
    const float* W0       = (const float*)d_in[2];
    const float* b0       = (const float*)d_in[3];
    const float* W1       = (const float*)d_in[4];
    const float* b1       = (const float*)d_in[5];
    const float* gamma    = (const float*)d_in[6];
    const float* beta     = (const float*)d_in[7];
    float* out = (float*)d_out;

    int V = in_sizes[0] / D;
    int E = in_sizes[1] / 2;
    float invV = 1.0f / (float)V;

    const int SMEM_BYTES = (128 * WS + 2 * GB_ROWS * D) * (int)sizeof(float);
    cudaFuncSetAttribute(gemm_dual, cudaFuncAttributeMaxDynamicSharedMemorySize, SMEM_BYTES);

    float* statsP = nullptr;
    cudaGetSymbolAddress((void**)&statsP, g_stats);

    zero_kernel<<<(V + 255) / 256, 256>>>(V);
    build_adj<<<(E + 255) / 256, 256>>>(edges, E);
    dinv_kernel<<<(V + 255) / 256, 256>>>(V);

    for (int l = 0; l < 3; l++) {
        const float* gPrev = (l == 0) ? nullptr : gamma + (size_t)(l - 1) * D;
        const float* bPrev = (l == 0) ? nullptr : beta  + (size_t)(l - 1) * D;
        gemm_dual<<<148, NTHR, SMEM_BYTES>>>(
            features, l,
            W0 + (size_t)l * D * D, b0 + (size_t)l * D,
            W1 + (size_t)l * D * D, b1 + (size_t)l * D,
            gPrev, bPrev, V, invV);

        agg_kernel<<<592, 256>>>(statsP + l * 2 * D, V);
    }

    norm_final<<<592, 256>>>(statsP + 2 * 2 * D,
                             gamma + 2 * (size_t)D, beta + 2 * (size_t)D,
                             features, out, V, invV);
}

// round 5
// speedup vs baseline: 1.5394x; 1.5394x over previous
#include <cuda_runtime.h>
#include <cuda_bf16.h>
#include <cstdint>

#define D 128
#define VCAP 100000
#define CAP 128
#define TM_ROWS 64         // rows per tensor tile (M)
#define TC_THR 256         // 8 warps
#define KS 136             // bf16 row stride (128 + 8 pad) -> conflict-free LDSM

// ---------------- scratch ----------------
__device__ float g_h0[(size_t)VCAP * D];
__device__ float g_h1[(size_t)VCAP * D];
__device__ float g_y [(size_t)VCAP * D];
__device__ int   g_adj[(size_t)VCAP * CAP];
__device__ int   g_cnt[VCAP];
__device__ float g_dinv[VCAP];
__device__ float g_stats[3 * 2 * D];

// ---------------- helpers ----------------
__device__ __forceinline__ uint32_t smem_u32(const void* p) {
    return (uint32_t)__cvta_generic_to_shared(p);
}
__device__ __forceinline__ uint32_t pack_bf(float a, float b) {
    __nv_bfloat162 h = __floats2bfloat162_rn(a, b);
    return *reinterpret_cast<uint32_t*>(&h);
}
__device__ __forceinline__ void ldsm_x4(uint32_t addr, uint32_t r[4]) {
    asm volatile("ldmatrix.sync.aligned.m8n8.x4.shared.b16 {%0,%1,%2,%3}, [%4];"
                 : "=r"(r[0]), "=r"(r[1]), "=r"(r[2]), "=r"(r[3]) : "r"(addr));
}
__device__ __forceinline__ void ldsm_x2(uint32_t addr, uint32_t r[2]) {
    asm volatile("ldmatrix.sync.aligned.m8n8.x2.shared.b16 {%0,%1}, [%2];"
                 : "=r"(r[0]), "=r"(r[1]) : "r"(addr));
}
__device__ __forceinline__ void mma_bf16(float c[4], const uint32_t a[4], const uint32_t b[2]) {
    asm volatile(
        "mma.sync.aligned.m16n8k16.row.col.f32.bf16.bf16.f32 "
        "{%0,%1,%2,%3}, {%4,%5,%6,%7}, {%8,%9}, {%0,%1,%2,%3};"
        : "+f"(c[0]), "+f"(c[1]), "+f"(c[2]), "+f"(c[3])
        : "r"(a[0]), "r"(a[1]), "r"(a[2]), "r"(a[3]), "r"(b[0]), "r"(b[1]));
}

// ---------------- prologue kernels ----------------
__global__ void zero_kernel(int V) {
    int i = blockIdx.x * blockDim.x + threadIdx.x;
    if (i < V) g_cnt[i] = 0;
    if (i < 3 * 2 * D) g_stats[i] = 0.0f;
}

__global__ void build_adj(const int* __restrict__ edges, int E) {
    int e = blockIdx.x * blockDim.x + threadIdx.x;
    if (e >= E) return;
    int a = edges[2 * e];
    int b = edges[2 * e + 1];
    int pa = atomicAdd(&g_cnt[a], 1);
    if (pa < CAP) g_adj[(size_t)a * CAP + pa] = b;
    int pb = atomicAdd(&g_cnt[b], 1);
    if (pb < CAP) g_adj[(size_t)b * CAP + pb] = a;
}

__global__ void dinv_kernel(int V) {
    int i = blockIdx.x * blockDim.x + threadIdx.x;
    if (i < V) g_dinv[i] = 1.0f / (1.0f + (float)g_cnt[i]);
}

// ---------------- HMMA dual GEMM (bf16x2 split, 3 terms) ----------------
// h0 = f(x) @ W0^T + b0 ; h1 = f(x) @ W1^T + b1 ; f = BN+ReLU of prev layer (l>0)
__global__ void __launch_bounds__(TC_THR, 1)
gemm_dual_tc(const float* __restrict__ xext, int layer,
             const float* __restrict__ W0, const float* __restrict__ b0,
             const float* __restrict__ W1, const float* __restrict__ b1,
             const float* __restrict__ gammaPrev, const float* __restrict__ betaPrev,
             int V, float invV)
{
    extern __shared__ __align__(16) char smb[];
    __nv_bfloat16* Bhi = (__nv_bfloat16*)smb;                       // [256][KS]
    __nv_bfloat16* Blo = Bhi + 256 * KS;                            // [256][KS]
    __nv_bfloat16* Ahi = Blo + 256 * KS;                            // [64][KS]
    __nv_bfloat16* Alo = Ahi + TM_ROWS * KS;                        // [64][KS]

    __shared__ float s_sc[D], s_sh[D], s_bias[256];

    const float* x = (layer == 0) ? xext : g_y;
    const bool doNorm = (layer != 0);

    int tid  = threadIdx.x;
    int wid  = tid >> 5;
    int lane = tid & 31;

    if (tid < D) {
        if (doNorm) {
            const float* st = g_stats + (layer - 1) * 2 * D;
            float mu  = st[tid] * invV;
            float var = st[D + tid] * invV - mu * mu;
            float rs  = rsqrtf(var + 1e-5f);
            float sc  = gammaPrev[tid] * rs;
            s_sc[tid] = sc;
            s_sh[tid] = betaPrev[tid] - mu * sc;
        }
        s_bias[tid]     = b0[tid];
        s_bias[tid + D] = b1[tid];
    }

    // --- convert W0||W1 -> Bhi/Blo (once per block) ---
    for (int idx = tid; idx < 256 * 32; idx += TC_THR) {
        int n  = idx >> 5;
        int k4 = (idx & 31) * 4;
        const float* Wp = (n < D) ? (W0 + (size_t)n * D + k4)
                                  : (W1 + (size_t)(n - D) * D + k4);
        float4 w = *(const float4*)Wp;
        float h0 = __bfloat162float(__float2bfloat16_rn(w.x));
        float h1 = __bfloat162float(__float2bfloat16_rn(w.y));
        float h2 = __bfloat162float(__float2bfloat16_rn(w.z));
        float h3 = __bfloat162float(__float2bfloat16_rn(w.w));
        *(uint2*)(Bhi + n * KS + k4) = make_uint2(pack_bf(h0, h1), pack_bf(h2, h3));
        *(uint2*)(Blo + n * KS + k4) = make_uint2(pack_bf(w.x - h0, w.y - h1),
                                                  pack_bf(w.z - h2, w.w - h3));
    }

    // warp tiling: mw = row group (16 rows), nw = col half (h0 vs h1)
    int mw = wid & 3;
    int nw = wid >> 2;
    int mrow0 = mw * 16;

    // ldmatrix lane addresses (byte offsets into bf16 arrays, x2 for bytes)
    uint32_t aOffB = (uint32_t)(((mrow0 + (lane & 15)) * KS + (lane >> 4) * 8) * 2);
    uint32_t aHiAddr = smem_u32(Ahi) + aOffB;
    uint32_t aLoAddr = smem_u32(Alo) + aOffB;
    uint32_t bOffB = (uint32_t)(((nw * 128 + (lane & 7)) * KS + ((lane >> 3) & 1) * 8) * 2);
    uint32_t bHiAddr = smem_u32(Bhi) + bOffB;
    uint32_t bLoAddr = smem_u32(Blo) + bOffB;

    // bias for this thread's n positions (same across nb via +8 step)
    // c-frag: c0 at n = nb*8 + 2*(lane&3), c1 at +1; c2,c3 same cols, row+8
    int ncol = (lane & 3) * 2;

    int numTiles = (V + TM_ROWS - 1) / TM_ROWS;
    for (int t = blockIdx.x; t < numTiles; t += gridDim.x) {
        int r0 = t * TM_ROWS;

        // --- convert x tile -> Ahi/Alo (fused BN+ReLU for layers 1,2) ---
        for (int idx = tid; idx < TM_ROWS * 32; idx += TC_THR) {
            int r  = idx >> 5;
            int k4 = (idx & 31) * 4;
            int row = r0 + r;
            float4 a = (row < V) ? *(const float4*)(x + (size_t)row * D + k4)
                                 : make_float4(0.f, 0.f, 0.f, 0.f);
            if (doNorm && row < V) {
                a.x = fmaxf(fmaf(a.x, s_sc[k4 + 0], s_sh[k4 + 0]), 0.f);
                a.y = fmaxf(fmaf(a.y, s_sc[k4 + 1], s_sh[k4 + 1]), 0.f);
                a.z = fmaxf(fmaf(a.z, s_sc[k4 + 2], s_sh[k4 + 2]), 0.f);
                a.w = fmaxf(fmaf(a.w, s_sc[k4 + 3], s_sh[k4 + 3]), 0.f);
            }
            float h0 = __bfloat162float(__float2bfloat16_rn(a.x));
            float h1 = __bfloat162float(__float2bfloat16_rn(a.y));
            float h2 = __bfloat162float(__float2bfloat16_rn(a.z));
            float h3 = __bfloat162float(__float2bfloat16_rn(a.w));
            *(uint2*)(Ahi + r * KS + k4) = make_uint2(pack_bf(h0, h1), pack_bf(h2, h3));
            *(uint2*)(Alo + r * KS + k4) = make_uint2(pack_bf(a.x - h0, a.y - h1),
                                                      pack_bf(a.z - h2, a.w - h3));
        }
        __syncthreads();

        // --- accumulators init to bias ---
        float acc[16][4];
        #pragma unroll
        for (int nb = 0; nb < 16; nb++) {
            float bx = s_bias[nw * 128 + nb * 8 + ncol];
            float by = s_bias[nw * 128 + nb * 8 + ncol + 1];
            acc[nb][0] = bx; acc[nb][1] = by;
            acc[nb][2] = bx; acc[nb][3] = by;
        }

        // --- main MMA loop: 8 k-chunks ---
        #pragma unroll
        for (int kc = 0; kc < 8; kc++) {
            uint32_t ahi[4], alo[4];
            ldsm_x4(aHiAddr + kc * 32, ahi);
            ldsm_x4(aLoAddr + kc * 32, alo);
            #pragma unroll
            for (int nb = 0; nb < 16; nb++) {
                uint32_t bhi[2], blo[2];
                uint32_t boff = (uint32_t)(nb * 8 * KS * 2 + kc * 32);
                ldsm_x2(bHiAddr + boff, bhi);
                ldsm_x2(bLoAddr + boff, blo);
                mma_bf16(acc[nb], ahi, bhi);
                mma_bf16(acc[nb], ahi, blo);
                mma_bf16(acc[nb], alo, bhi);
            }
        }

        // --- epilogue: store to g_h0 / g_h1 ---
        int rA = r0 + mrow0 + (lane >> 2);
        int rB = rA + 8;
        float* dst = (nw == 0) ? g_h0 : g_h1;
        #pragma unroll
        for (int nb = 0; nb < 16; nb++) {
            int c = nb * 8 + ncol;
            if (rA < V) *(float2*)(dst + (size_t)rA * D + c) = make_float2(acc[nb][0], acc[nb][1]);
            if (rB < V) *(float2*)(dst + (size_t)rB * D + c) = make_float2(acc[nb][2], acc[nb][3]);
        }
        __syncthreads();   // done reading A tiles before next conversion
    }
}

// ---------------- aggregation + BN stats ----------------
__global__ void __launch_bounds__(256) agg_kernel(float* __restrict__ stats, int V)
{
    __shared__ float s_sum[D];
    __shared__ float s_sq[D];

    int tid  = threadIdx.x;
    int wid  = tid >> 5;
    int lane = tid & 31;
    int c0   = lane * 4;

    if (tid < D) { s_sum[tid] = 0.f; s_sq[tid] = 0.f; }
    __syncthreads();

    float4 psum = make_float4(0.f, 0.f, 0.f, 0.f);
    float4 psq  = make_float4(0.f, 0.f, 0.f, 0.f);

    int warpStride = gridDim.x * 8;
    for (int v = blockIdx.x * 8 + wid; v < V; v += warpStride) {
        float4 acc = *(const float4*)(g_h0 + (size_t)v * D + c0);
        int n = g_cnt[v];
        const int* ap = g_adj + (size_t)v * CAP;
        int e = 0;
        for (; e + 1 < n; e += 2) {
            int u0 = ap[e];
            int u1 = ap[e + 1];
            float4 t0 = *(const float4*)(g_h1 + (size_t)u0 * D + c0);
            float4 t1 = *(const float4*)(g_h1 + (size_t)u1 * D + c0);
            acc.x += t0.x + t1.x;
            acc.y += t0.y + t1.y;
            acc.z += t0.z + t1.z;
            acc.w += t0.w + t1.w;
        }
        if (e < n) {
            int u = ap[e];
            float4 t = *(const float4*)(g_h1 + (size_t)u * D + c0);
            acc.x += t.x; acc.y += t.y; acc.z += t.z; acc.w += t.w;
        }
        float dv = g_dinv[v];
        acc.x *= dv; acc.y *= dv; acc.z *= dv; acc.w *= dv;
        *(float4*)(g_y + (size_t)v * D + c0) = acc;

        psum.x += acc.x; psum.y += acc.y; psum.z += acc.z; psum.w += acc.w;
        psq.x  += acc.x * acc.x; psq.y += acc.y * acc.y;
        psq.z  += acc.z * acc.z; psq.w += acc.w * acc.w;
    }

    atomicAdd(&s_sum[c0 + 0], psum.x);
    atomicAdd(&s_sum[c0 + 1], psum.y);
    atomicAdd(&s_sum[c0 + 2], psum.z);
    atomicAdd(&s_sum[c0 + 3], psum.w);
    atomicAdd(&s_sq[c0 + 0],  psq.x);
    atomicAdd(&s_sq[c0 + 1],  psq.y);
    atomicAdd(&s_sq[c0 + 2],  psq.z);
    atomicAdd(&s_sq[c0 + 3],  psq.w);
    __syncthreads();

    if (tid < D) {
        atomicAdd(&stats[tid],     s_sum[tid]);
        atomicAdd(&stats[D + tid], s_sq[tid]);
    }
}

// ---------------- final BN + ReLU + residual -> out ----------------
__global__ void __launch_bounds__(256) norm_final(
    const float* __restrict__ stats,
    const float* __restrict__ gamma, const float* __restrict__ beta,
    const float* __restrict__ res,
    float* __restrict__ out, int V, float invV)
{
    __shared__ float s_scale[D];
    __shared__ float s_shift[D];

    int tid = threadIdx.x;
    if (tid < D) {
        float mu  = stats[tid] * invV;
        float var = stats[D + tid] * invV - mu * mu;
        float rs  = rsqrtf(var + 1e-5f);
        float sc  = gamma[tid] * rs;
        s_scale[tid] = sc;
        s_shift[tid] = beta[tid] - mu * sc;
    }
    __syncthreads();

    int total = V * (D / 4);
    for (int f = blockIdx.x * blockDim.x + tid; f < total; f += gridDim.x * blockDim.x) {
        int c = (f & 31) * 4;
        float4 t = *(const float4*)(g_y + (size_t)f * 4);
        float4 r = *(const float4*)(res + (size_t)f * 4);
        float4 o;
        o.x = fmaxf(fmaf(t.x, s_scale[c + 0], s_shift[c + 0]) + r.x, 0.f);
        o.y = fmaxf(fmaf(t.y, s_scale[c + 1], s_shift[c + 1]) + r.y, 0.f);
        o.z = fmaxf(fmaf(t.z, s_scale[c + 2], s_shift[c + 2]) + r.z, 0.f);
        o.w = fmaxf(fmaf(t.w, s_scale[c + 3], s_shift[c + 3]) + r.w, 0.f);
        *(float4*)(out + (size_t)f * 4) = o;
    }
}

// ---------------- launch ----------------
extern "C" void kernel_launch(void* const* d_in, const int* in_sizes, int n_in,
                              void* d_out, int out_size)
{
    const float* features = (const float*)d_in[0];
    const int*   edges    = (const int*)  d_in[1];
    const float* W0       = (const float*)d_in[2];
    const float* b0       = (const float*)d_in[3];
    const float* W1       = (const float*)d_in[4];
    const float* b1       = (const float*)d_in[5];
    const float* gamma    = (const float*)d_in[6];
    const float* beta     = (const float*)d_in[7];
    float* out = (float*)d_out;

    int V = in_sizes[0] / D;
    int E = in_sizes[1] / 2;
    float invV = 1.0f / (float)V;

    // 2*(256*KS) + 2*(64*KS) bf16 = (2*256 + 2*64) * 136 * 2 bytes
    const int SMEM_BYTES = (2 * 256 + 2 * TM_ROWS) * KS * 2;
    cudaFuncSetAttribute(gemm_dual_tc, cudaFuncAttributeMaxDynamicSharedMemorySize, SMEM_BYTES);

    float* statsP = nullptr;
    cudaGetSymbolAddress((void**)&statsP, g_stats);

    zero_kernel<<<(V + 255) / 256, 256>>>(V);
    build_adj<<<(E + 255) / 256, 256>>>(edges, E);
    dinv_kernel<<<(V + 255) / 256, 256>>>(V);

    for (int l = 0; l < 3; l++) {
        const float* gPrev = (l == 0) ? nullptr : gamma + (size_t)(l - 1) * D;
        const float* bPrev = (l == 0) ? nullptr : beta  + (size_t)(l - 1) * D;
        gemm_dual_tc<<<148, TC_THR, SMEM_BYTES>>>(
            features, l,
            W0 + (size_t)l * D * D, b0 + (size_t)l * D,
            W1 + (size_t)l * D * D, b1 + (size_t)l * D,
            gPrev, bPrev, V, invV);

        agg_kernel<<<592, 256>>>(statsP + l * 2 * D, V);
    }

    norm_final<<<592, 256>>>(statsP + 2 * 2 * D,
                             gamma + 2 * (size_t)D, beta + 2 * (size_t)D,
                             features, out, V, invV);
}

// round 6
// speedup vs baseline: 1.5792x; 1.0259x over previous
#include <cuda_runtime.h>
#include <cuda_bf16.h>
#include <cstdint>

#define D 128
#define VCAP 100000
#define CAP 128
#define TM_ROWS 96         // rows per tensor tile (M)
#define TC_THR 384         // 12 warps: 6 row groups x 2 col halves
#define KS 136             // bf16 row stride (128 + 8 pad) -> conflict-free LDSM

// ---------------- scratch ----------------
__device__ float g_h0[(size_t)VCAP * D];
__device__ float g_h1[(size_t)VCAP * D];
__device__ float g_y [(size_t)VCAP * D];
__device__ int   g_adj[(size_t)VCAP * CAP];
__device__ int   g_cnt[VCAP];
__device__ float g_dinv[VCAP];
__device__ float g_stats[3 * 2 * D];

// ---------------- helpers ----------------
__device__ __forceinline__ uint32_t smem_u32(const void* p) {
    return (uint32_t)__cvta_generic_to_shared(p);
}
__device__ __forceinline__ uint32_t pack_bf(float a, float b) {
    __nv_bfloat162 h = __floats2bfloat162_rn(a, b);
    return *reinterpret_cast<uint32_t*>(&h);
}
__device__ __forceinline__ void ldsm_x4(uint32_t addr, uint32_t r[4]) {
    asm volatile("ldmatrix.sync.aligned.m8n8.x4.shared.b16 {%0,%1,%2,%3}, [%4];"
                 : "=r"(r[0]), "=r"(r[1]), "=r"(r[2]), "=r"(r[3]) : "r"(addr));
}
__device__ __forceinline__ void ldsm_x2(uint32_t addr, uint32_t r[2]) {
    asm volatile("ldmatrix.sync.aligned.m8n8.x2.shared.b16 {%0,%1}, [%2];"
                 : "=r"(r[0]), "=r"(r[1]) : "r"(addr));
}
__device__ __forceinline__ void mma_bf16(float c[4], const uint32_t a[4], const uint32_t b[2]) {
    asm volatile(
        "mma.sync.aligned.m16n8k16.row.col.f32.bf16.bf16.f32 "
        "{%0,%1,%2,%3}, {%4,%5,%6,%7}, {%8,%9}, {%0,%1,%2,%3};"
        : "+f"(c[0]), "+f"(c[1]), "+f"(c[2]), "+f"(c[3])
        : "r"(a[0]), "r"(a[1]), "r"(a[2]), "r"(a[3]), "r"(b[0]), "r"(b[1]));
}

// ---------------- prologue kernels ----------------
__global__ void zero_kernel(int V) {
    int i = blockIdx.x * blockDim.x + threadIdx.x;
    if (i < V) g_cnt[i] = 0;
    if (i < 3 * 2 * D) g_stats[i] = 0.0f;
}

__global__ void build_adj(const int* __restrict__ edges, int E) {
    int e = blockIdx.x * blockDim.x + threadIdx.x;
    if (e >= E) return;
    int a = edges[2 * e];
    int b = edges[2 * e + 1];
    int pa = atomicAdd(&g_cnt[a], 1);
    if (pa < CAP) g_adj[(size_t)a * CAP + pa] = b;
    int pb = atomicAdd(&g_cnt[b], 1);
    if (pb < CAP) g_adj[(size_t)b * CAP + pb] = a;
}

__global__ void dinv_kernel(int V) {
    int i = blockIdx.x * blockDim.x + threadIdx.x;
    if (i < V) g_dinv[i] = 1.0f / (1.0f + (float)g_cnt[i]);
}

// ---------------- HMMA dual GEMM (bf16x2 split, 3 terms) ----------------
// h0 = f(x) @ W0^T + b0 ; h1 = f(x) @ W1^T + b1 ; f = BN+ReLU of prev layer (l>0)
__global__ void __launch_bounds__(TC_THR, 1)
gemm_dual_tc(const float* __restrict__ xext, int layer,
             const float* __restrict__ W0, const float* __restrict__ b0,
             const float* __restrict__ W1, const float* __restrict__ b1,
             const float* __restrict__ gammaPrev, const float* __restrict__ betaPrev,
             int V, float invV)
{
    extern __shared__ __align__(16) char smb[];
    __nv_bfloat16* Bhi = (__nv_bfloat16*)smb;                       // [256][KS]
    __nv_bfloat16* Blo = Bhi + 256 * KS;                            // [256][KS]
    __nv_bfloat16* Ahi = Blo + 256 * KS;                            // [96][KS]
    __nv_bfloat16* Alo = Ahi + TM_ROWS * KS;                        // [96][KS]

    __shared__ float s_sc[D], s_sh[D], s_bias[256];

    const float* x = (layer == 0) ? xext : g_y;
    const bool doNorm = (layer != 0);

    int tid  = threadIdx.x;
    int wid  = tid >> 5;
    int lane = tid & 31;

    if (tid < D) {
        if (doNorm) {
            const float* st = g_stats + (layer - 1) * 2 * D;
            float mu  = st[tid] * invV;
            float var = st[D + tid] * invV - mu * mu;
            float rs  = rsqrtf(var + 1e-5f);
            float sc  = gammaPrev[tid] * rs;
            s_sc[tid] = sc;
            s_sh[tid] = betaPrev[tid] - mu * sc;
        }
        s_bias[tid]     = b0[tid];
        s_bias[tid + D] = b1[tid];
    }

    // --- convert W0||W1 -> Bhi/Blo (once per block) ---
    for (int idx = tid; idx < 256 * 32; idx += TC_THR) {
        int n  = idx >> 5;
        int k4 = (idx & 31) * 4;
        const float* Wp = (n < D) ? (W0 + (size_t)n * D + k4)
                                  : (W1 + (size_t)(n - D) * D + k4);
        float4 w = *(const float4*)Wp;
        float h0 = __bfloat162float(__float2bfloat16_rn(w.x));
        float h1 = __bfloat162float(__float2bfloat16_rn(w.y));
        float h2 = __bfloat162float(__float2bfloat16_rn(w.z));
        float h3 = __bfloat162float(__float2bfloat16_rn(w.w));
        *(uint2*)(Bhi + n * KS + k4) = make_uint2(pack_bf(h0, h1), pack_bf(h2, h3));
        *(uint2*)(Blo + n * KS + k4) = make_uint2(pack_bf(w.x - h0, w.y - h1),
                                                  pack_bf(w.z - h2, w.w - h3));
    }

    // warp tiling: mw = row group (16 rows, 0..5), nw = col half (h0 vs h1)
    int mw = wid >> 1;
    int nw = wid & 1;
    int mrow0 = mw * 16;

    // ldmatrix lane addresses
    uint32_t aOffB = (uint32_t)(((mrow0 + (lane & 15)) * KS + (lane >> 4) * 8) * 2);
    uint32_t aHiAddr = smem_u32(Ahi) + aOffB;
    uint32_t aLoAddr = smem_u32(Alo) + aOffB;
    uint32_t bOffB = (uint32_t)(((nw * 128 + (lane & 7)) * KS + ((lane >> 3) & 1) * 8) * 2);
    uint32_t bHiAddr = smem_u32(Bhi) + bOffB;
    uint32_t bLoAddr = smem_u32(Blo) + bOffB;

    int ncol = (lane & 3) * 2;

    int numTiles = (V + TM_ROWS - 1) / TM_ROWS;
    for (int t = blockIdx.x; t < numTiles; t += gridDim.x) {
        int r0 = t * TM_ROWS;

        // --- convert x tile -> Ahi/Alo (fused BN+ReLU for layers 1,2) ---
        for (int idx = tid; idx < TM_ROWS * 32; idx += TC_THR) {
            int r  = idx >> 5;
            int k4 = (idx & 31) * 4;
            int row = r0 + r;
            float4 a = (row < V) ? *(const float4*)(x + (size_t)row * D + k4)
                                 : make_float4(0.f, 0.f, 0.f, 0.f);
            if (doNorm && row < V) {
                a.x = fmaxf(fmaf(a.x, s_sc[k4 + 0], s_sh[k4 + 0]), 0.f);
                a.y = fmaxf(fmaf(a.y, s_sc[k4 + 1], s_sh[k4 + 1]), 0.f);
                a.z = fmaxf(fmaf(a.z, s_sc[k4 + 2], s_sh[k4 + 2]), 0.f);
                a.w = fmaxf(fmaf(a.w, s_sc[k4 + 3], s_sh[k4 + 3]), 0.f);
            }
            float h0 = __bfloat162float(__float2bfloat16_rn(a.x));
            float h1 = __bfloat162float(__float2bfloat16_rn(a.y));
            float h2 = __bfloat162float(__float2bfloat16_rn(a.z));
            float h3 = __bfloat162float(__float2bfloat16_rn(a.w));
            *(uint2*)(Ahi + r * KS + k4) = make_uint2(pack_bf(h0, h1), pack_bf(h2, h3));
            *(uint2*)(Alo + r * KS + k4) = make_uint2(pack_bf(a.x - h0, a.y - h1),
                                                      pack_bf(a.z - h2, a.w - h3));
        }
        __syncthreads();

        // --- accumulators init to bias ---
        float acc[16][4];
        #pragma unroll
        for (int nb = 0; nb < 16; nb++) {
            float bx = s_bias[nw * 128 + nb * 8 + ncol];
            float by = s_bias[nw * 128 + nb * 8 + ncol + 1];
            acc[nb][0] = bx; acc[nb][1] = by;
            acc[nb][2] = bx; acc[nb][3] = by;
        }

        // --- main MMA loop: 8 k-chunks ---
        #pragma unroll
        for (int kc = 0; kc < 8; kc++) {
            uint32_t ahi[4], alo[4];
            ldsm_x4(aHiAddr + kc * 32, ahi);
            ldsm_x4(aLoAddr + kc * 32, alo);
            #pragma unroll
            for (int nb = 0; nb < 16; nb++) {
                uint32_t bhi[2], blo[2];
                uint32_t boff = (uint32_t)(nb * 8 * KS * 2 + kc * 32);
                ldsm_x2(bHiAddr + boff, bhi);
                ldsm_x2(bLoAddr + boff, blo);
                mma_bf16(acc[nb], ahi, bhi);
                mma_bf16(acc[nb], ahi, blo);
                mma_bf16(acc[nb], alo, bhi);
            }
        }

        // --- epilogue: store to g_h0 / g_h1 ---
        int rA = r0 + mrow0 + (lane >> 2);
        int rB = rA + 8;
        float* dst = (nw == 0) ? g_h0 : g_h1;
        #pragma unroll
        for (int nb = 0; nb < 16; nb++) {
            int c = nb * 8 + ncol;
            if (rA < V) *(float2*)(dst + (size_t)rA * D + c) = make_float2(acc[nb][0], acc[nb][1]);
            if (rB < V) *(float2*)(dst + (size_t)rB * D + c) = make_float2(acc[nb][2], acc[nb][3]);
        }
        __syncthreads();   // done reading A tiles before next conversion
    }
}

// ---------------- aggregation + BN stats ----------------
__global__ void __launch_bounds__(256) agg_kernel(float* __restrict__ stats, int V)
{
    __shared__ float s_sum[D];
    __shared__ float s_sq[D];

    int tid  = threadIdx.x;
    int wid  = tid >> 5;
    int lane = tid & 31;
    int c0   = lane * 4;

    if (tid < D) { s_sum[tid] = 0.f; s_sq[tid] = 0.f; }
    __syncthreads();

    float4 psum = make_float4(0.f, 0.f, 0.f, 0.f);
    float4 psq  = make_float4(0.f, 0.f, 0.f, 0.f);

    int warpStride = gridDim.x * 8;
    for (int v = blockIdx.x * 8 + wid; v < V; v += warpStride) {
        float4 acc = *(const float4*)(g_h0 + (size_t)v * D + c0);
        int n = g_cnt[v];
        const int* ap = g_adj + (size_t)v * CAP;
        int e = 0;
        for (; e + 3 < n; e += 4) {
            int u0 = ap[e], u1 = ap[e + 1], u2 = ap[e + 2], u3 = ap[e + 3];
            float4 t0 = __ldg((const float4*)(g_h1 + (size_t)u0 * D + c0));
            float4 t1 = __ldg((const float4*)(g_h1 + (size_t)u1 * D + c0));
            float4 t2 = __ldg((const float4*)(g_h1 + (size_t)u2 * D + c0));
            float4 t3 = __ldg((const float4*)(g_h1 + (size_t)u3 * D + c0));
            acc.x += (t0.x + t1.x) + (t2.x + t3.x);
            acc.y += (t0.y + t1.y) + (t2.y + t3.y);
            acc.z += (t0.z + t1.z) + (t2.z + t3.z);
            acc.w += (t0.w + t1.w) + (t2.w + t3.w);
        }
        for (; e < n; e++) {
            int u = ap[e];
            float4 t = __ldg((const float4*)(g_h1 + (size_t)u * D + c0));
            acc.x += t.x; acc.y += t.y; acc.z += t.z; acc.w += t.w;
        }
        float dv = g_dinv[v];
        acc.x *= dv; acc.y *= dv; acc.z *= dv; acc.w *= dv;
        *(float4*)(g_y + (size_t)v * D + c0) = acc;

        psum.x += acc.x; psum.y += acc.y; psum.z += acc.z; psum.w += acc.w;
        psq.x  += acc.x * acc.x; psq.y += acc.y * acc.y;
        psq.z  += acc.z * acc.z; psq.w += acc.w * acc.w;
    }

    atomicAdd(&s_sum[c0 + 0], psum.x);
    atomicAdd(&s_sum[c0 + 1], psum.y);
    atomicAdd(&s_sum[c0 + 2], psum.z);
    atomicAdd(&s_sum[c0 + 3], psum.w);
    atomicAdd(&s_sq[c0 + 0],  psq.x);
    atomicAdd(&s_sq[c0 + 1],  psq.y);
    atomicAdd(&s_sq[c0 + 2],  psq.z);
    atomicAdd(&s_sq[c0 + 3],  psq.w);
    __syncthreads();

    if (tid < D) {
        atomicAdd(&stats[tid],     s_sum[tid]);
        atomicAdd(&stats[D + tid], s_sq[tid]);
    }
}

// ---------------- final BN + ReLU + residual -> out ----------------
__global__ void __launch_bounds__(256) norm_final(
    const float* __restrict__ stats,
    const float* __restrict__ gamma, const float* __restrict__ beta,
    const float* __restrict__ res,
    float* __restrict__ out, int V, float invV)
{
    __shared__ float s_scale[D];
    __shared__ float s_shift[D];

    int tid = threadIdx.x;
    if (tid < D) {
        float mu  = stats[tid] * invV;
        float var = stats[D + tid] * invV - mu * mu;
        float rs  = rsqrtf(var + 1e-5f);
        float sc  = gamma[tid] * rs;
        s_scale[tid] = sc;
        s_shift[tid] = beta[tid] - mu * sc;
    }
    __syncthreads();

    int total = V * (D / 4);
    for (int f = blockIdx.x * blockDim.x + tid; f < total; f += gridDim.x * blockDim.x) {
        int c = (f & 31) * 4;
        float4 t = *(const float4*)(g_y + (size_t)f * 4);
        float4 r = *(const float4*)(res + (size_t)f * 4);
        float4 o;
        o.x = fmaxf(fmaf(t.x, s_scale[c + 0], s_shift[c + 0]) + r.x, 0.f);
        o.y = fmaxf(fmaf(t.y, s_scale[c + 1], s_shift[c + 1]) + r.y, 0.f);
        o.z = fmaxf(fmaf(t.z, s_scale[c + 2], s_shift[c + 2]) + r.z, 0.f);
        o.w = fmaxf(fmaf(t.w, s_scale[c + 3], s_shift[c + 3]) + r.w, 0.f);
        *(float4*)(out + (size_t)f * 4) = o;
    }
}

// ---------------- launch ----------------
extern "C" void kernel_launch(void* const* d_in, const int* in_sizes, int n_in,
                              void* d_out, int out_size)
{
    const float* features = (const float*)d_in[0];
    const int*   edges    = (const int*)  d_in[1];
    const float* W0       = (const float*)d_in[2];
    const float* b0       = (const float*)d_in[3];
    const float* W1       = (const float*)d_in[4];
    const float* b1       = (const float*)d_in[5];
    const float* gamma    = (const float*)d_in[6];
    const float* beta     = (const float*)d_in[7];
    float* out = (float*)d_out;

    int V = in_sizes[0] / D;
    int E = in_sizes[1] / 2;
    float invV = 1.0f / (float)V;

    const int SMEM_BYTES = (2 * 256 + 2 * TM_ROWS) * KS * 2;
    cudaFuncSetAttribute(gemm_dual_tc, cudaFuncAttributeMaxDynamicSharedMemorySize, SMEM_BYTES);

    float* statsP = nullptr;
    cudaGetSymbolAddress((void**)&statsP, g_stats);

    zero_kernel<<<(V + 255) / 256, 256>>>(V);
    build_adj<<<(E + 255) / 256, 256>>>(edges, E);
    dinv_kernel<<<(V + 255) / 256, 256>>>(V);

    for (int l = 0; l < 3; l++) {
        const float* gPrev = (l == 0) ? nullptr : gamma + (size_t)(l - 1) * D;
        const float* bPrev = (l == 0) ? nullptr : beta  + (size_t)(l - 1) * D;
        gemm_dual_tc<<<148, TC_THR, SMEM_BYTES>>>(
            features, l,
            W0 + (size_t)l * D * D, b0 + (size_t)l * D,
            W1 + (size_t)l * D * D, b1 + (size_t)l * D,
            gPrev, bPrev, V, invV);

        agg_kernel<<<592, 256>>>(statsP + l * 2 * D, V);
    }

    norm_final<<<592, 256>>>(statsP + 2 * 2 * D,
                             gamma + 2 * (size_t)D, beta + 2 * (size_t)D,
                             features, out, V, invV);
}

// round 7
// speedup vs baseline: 1.7187x; 1.0883x over previous
#include <cuda_runtime.h>
#include <cuda_bf16.h>
#include <cstdint>

#define D 128
#define VCAP 100000
#define CAP 128
#define TM_ROWS 96         // rows per tensor tile (M)
#define TC_THR 384         // 12 warps: 3 row groups (32 rows) x 4 col groups (64 cols)
#define KS 136             // bf16 row stride (128 + 8 pad) -> conflict-free LDSM

// ---------------- scratch ----------------
__device__ float g_h0[(size_t)VCAP * D];
__device__ float g_h1[(size_t)VCAP * D];
__device__ float g_y [(size_t)VCAP * D];
__device__ int   g_adj[(size_t)VCAP * CAP];
__device__ int   g_cnt[VCAP];
__device__ float g_dinv[VCAP];
__device__ float g_stats[3 * 2 * D];

// ---------------- helpers ----------------
__device__ __forceinline__ uint32_t smem_u32(const void* p) {
    return (uint32_t)__cvta_generic_to_shared(p);
}
__device__ __forceinline__ uint32_t pack_bf(float a, float b) {
    __nv_bfloat162 h = __floats2bfloat162_rn(a, b);
    return *reinterpret_cast<uint32_t*>(&h);
}
__device__ __forceinline__ void ldsm_x4(uint32_t addr, uint32_t r[4]) {
    asm volatile("ldmatrix.sync.aligned.m8n8.x4.shared.b16 {%0,%1,%2,%3}, [%4];"
                 : "=r"(r[0]), "=r"(r[1]), "=r"(r[2]), "=r"(r[3]) : "r"(addr));
}
__device__ __forceinline__ void mma_bf16(float c[4], const uint32_t a[4],
                                         uint32_t b0, uint32_t b1) {
    asm volatile(
        "mma.sync.aligned.m16n8k16.row.col.f32.bf16.bf16.f32 "
        "{%0,%1,%2,%3}, {%4,%5,%6,%7}, {%8,%9}, {%0,%1,%2,%3};"
        : "+f"(c[0]), "+f"(c[1]), "+f"(c[2]), "+f"(c[3])
        : "r"(a[0]), "r"(a[1]), "r"(a[2]), "r"(a[3]), "r"(b0), "r"(b1));
}

// ---------------- prologue kernels ----------------
__global__ void zero_kernel(int V) {
    int i = blockIdx.x * blockDim.x + threadIdx.x;
    if (i < V) g_cnt[i] = 0;
    if (i < 3 * 2 * D) g_stats[i] = 0.0f;
}

__global__ void build_adj(const int* __restrict__ edges, int E) {
    int e = blockIdx.x * blockDim.x + threadIdx.x;
    if (e >= E) return;
    int a = edges[2 * e];
    int b = edges[2 * e + 1];
    int pa = atomicAdd(&g_cnt[a], 1);
    if (pa < CAP) g_adj[(size_t)a * CAP + pa] = b;
    int pb = atomicAdd(&g_cnt[b], 1);
    if (pb < CAP) g_adj[(size_t)b * CAP + pb] = a;
}

__global__ void dinv_kernel(int V) {
    int i = blockIdx.x * blockDim.x + threadIdx.x;
    if (i < V) g_dinv[i] = 1.0f / (1.0f + (float)g_cnt[i]);
}

// ---------------- HMMA dual GEMM (bf16x2 split, 3 terms) ----------------
// h0 = f(x) @ W0^T + b0 ; h1 = f(x) @ W1^T + b1 ; f = BN+ReLU of prev layer (l>0)
__global__ void __launch_bounds__(TC_THR, 1)
gemm_dual_tc(const float* __restrict__ xext, int layer,
             const float* __restrict__ W0, const float* __restrict__ b0,
             const float* __restrict__ W1, const float* __restrict__ b1,
             const float* __restrict__ gammaPrev, const float* __restrict__ betaPrev,
             int V, float invV)
{
    extern __shared__ __align__(16) char smb[];
    __nv_bfloat16* Bhi = (__nv_bfloat16*)smb;                       // [256][KS]
    __nv_bfloat16* Blo = Bhi + 256 * KS;                            // [256][KS]
    __nv_bfloat16* Ahi = Blo + 256 * KS;                            // [96][KS]
    __nv_bfloat16* Alo = Ahi + TM_ROWS * KS;                        // [96][KS]

    __shared__ float s_sc[D], s_sh[D], s_bias[256];

    const float* x = (layer == 0) ? xext : g_y;
    const bool doNorm = (layer != 0);

    int tid  = threadIdx.x;
    int wid  = tid >> 5;
    int lane = tid & 31;

    if (tid < D) {
        if (doNorm) {
            const float* st = g_stats + (layer - 1) * 2 * D;
            float mu  = st[tid] * invV;
            float var = st[D + tid] * invV - mu * mu;
            float rs  = rsqrtf(var + 1e-5f);
            float sc  = gammaPrev[tid] * rs;
            s_sc[tid] = sc;
            s_sh[tid] = betaPrev[tid] - mu * sc;
        }
        s_bias[tid]     = b0[tid];
        s_bias[tid + D] = b1[tid];
    }

    // --- convert W0||W1 -> Bhi/Blo (once per block) ---
    for (int idx = tid; idx < 256 * 32; idx += TC_THR) {
        int n  = idx >> 5;
        int k4 = (idx & 31) * 4;
        const float* Wp = (n < D) ? (W0 + (size_t)n * D + k4)
                                  : (W1 + (size_t)(n - D) * D + k4);
        float4 w = *(const float4*)Wp;
        float h0 = __bfloat162float(__float2bfloat16_rn(w.x));
        float h1 = __bfloat162float(__float2bfloat16_rn(w.y));
        float h2 = __bfloat162float(__float2bfloat16_rn(w.z));
        float h3 = __bfloat162float(__float2bfloat16_rn(w.w));
        *(uint2*)(Bhi + n * KS + k4) = make_uint2(pack_bf(h0, h1), pack_bf(h2, h3));
        *(uint2*)(Blo + n * KS + k4) = make_uint2(pack_bf(w.x - h0, w.y - h1),
                                                  pack_bf(w.z - h2, w.w - h3));
    }

    // warp tiling: mw = row group (32 rows, 0..2), nw = col group (64 cols, 0..3)
    int mw = wid >> 2;
    int nw = wid & 3;
    int mrow0 = mw * 32;
    int ncolbase = nw * 64;     // within 0..255

    // A ldmatrix addresses: two 16-row sets
    uint32_t aOffB = (uint32_t)(((mrow0 + (lane & 15)) * KS + (lane >> 4) * 8) * 2);
    uint32_t aHiAddr0 = smem_u32(Ahi) + aOffB;
    uint32_t aLoAddr0 = smem_u32(Alo) + aOffB;
    uint32_t aHiAddr1 = aHiAddr0 + 16 * KS * 2;
    uint32_t aLoAddr1 = aLoAddr0 + 16 * KS * 2;

    // B ldmatrix x4 addresses: 16 n-rows per load (2 n-groups of 8)
    uint32_t bOffB = (uint32_t)(((ncolbase + (lane & 15)) * KS + (lane >> 4) * 8) * 2);
    uint32_t bHiAddr = smem_u32(Bhi) + bOffB;
    uint32_t bLoAddr = smem_u32(Blo) + bOffB;

    int ncol = (lane & 3) * 2;

    int numTiles = (V + TM_ROWS - 1) / TM_ROWS;
    int tFirst = blockIdx.x;

    // --- register prefetch of first tile ---
    float4 pf[8];
    {
        int r0 = tFirst * TM_ROWS;
        #pragma unroll
        for (int it = 0; it < 8; it++) {
            int f   = tid + it * TC_THR;
            int row = r0 + (f >> 5);
            int k4  = (f & 31) * 4;
            pf[it] = (tFirst < numTiles && row < V)
                   ? *(const float4*)(x + (size_t)row * D + k4)
                   : make_float4(0.f, 0.f, 0.f, 0.f);
        }
    }

    for (int t = tFirst; t < numTiles; t += gridDim.x) {
        int r0 = t * TM_ROWS;

        // --- convert prefetched x tile -> Ahi/Alo (fused BN+ReLU for layers 1,2) ---
        #pragma unroll
        for (int it = 0; it < 8; it++) {
            int f  = tid + it * TC_THR;
            int r  = f >> 5;
            int k4 = (f & 31) * 4;
            float4 a = pf[it];
            if (doNorm) {
                a.x = fmaxf(fmaf(a.x, s_sc[k4 + 0], s_sh[k4 + 0]), 0.f);
                a.y = fmaxf(fmaf(a.y, s_sc[k4 + 1], s_sh[k4 + 1]), 0.f);
                a.z = fmaxf(fmaf(a.z, s_sc[k4 + 2], s_sh[k4 + 2]), 0.f);
                a.w = fmaxf(fmaf(a.w, s_sc[k4 + 3], s_sh[k4 + 3]), 0.f);
                if (r0 + r >= V) a = make_float4(0.f, 0.f, 0.f, 0.f);
            }
            float h0 = __bfloat162float(__float2bfloat16_rn(a.x));
            float h1 = __bfloat162float(__float2bfloat16_rn(a.y));
            float h2 = __bfloat162float(__float2bfloat16_rn(a.z));
            float h3 = __bfloat162float(__float2bfloat16_rn(a.w));
            *(uint2*)(Ahi + r * KS + k4) = make_uint2(pack_bf(h0, h1), pack_bf(h2, h3));
            *(uint2*)(Alo + r * KS + k4) = make_uint2(pack_bf(a.x - h0, a.y - h1),
                                                      pack_bf(a.z - h2, a.w - h3));
        }
        __syncthreads();

        // --- prefetch next tile (latency hidden under MMA loop) ---
        int tn = t + gridDim.x;
        if (tn < numTiles) {
            int rn0 = tn * TM_ROWS;
            #pragma unroll
            for (int it = 0; it < 8; it++) {
                int f   = tid + it * TC_THR;
                int row = rn0 + (f >> 5);
                int k4  = (f & 31) * 4;
                pf[it] = (row < V) ? *(const float4*)(x + (size_t)row * D + k4)
                                   : make_float4(0.f, 0.f, 0.f, 0.f);
            }
        }

        // --- accumulators init to bias: acc[n][0..3] rowset0, [4..7] rowset1 ---
        float acc[8][8];
        #pragma unroll
        for (int n = 0; n < 8; n++) {
            float bx = s_bias[ncolbase + n * 8 + ncol];
            float by = s_bias[ncolbase + n * 8 + ncol + 1];
            acc[n][0] = bx; acc[n][1] = by; acc[n][2] = bx; acc[n][3] = by;
            acc[n][4] = bx; acc[n][5] = by; acc[n][6] = bx; acc[n][7] = by;
        }

        // --- main MMA loop: 8 k-chunks ---
        #pragma unroll
        for (int kc = 0; kc < 8; kc++) {
            uint32_t ahi0[4], alo0[4], ahi1[4], alo1[4];
            ldsm_x4(aHiAddr0 + kc * 32, ahi0);
            ldsm_x4(aLoAddr0 + kc * 32, alo0);
            ldsm_x4(aHiAddr1 + kc * 32, ahi1);
            ldsm_x4(aLoAddr1 + kc * 32, alo1);
            #pragma unroll
            for (int np = 0; np < 4; np++) {
                uint32_t bhi[4], blo[4];
                uint32_t boff = (uint32_t)(np * 16 * KS * 2 + kc * 32);
                ldsm_x4(bHiAddr + boff, bhi);
                ldsm_x4(bLoAddr + boff, blo);
                // n even = {bhi[0], bhi[2]}, n odd = {bhi[1], bhi[3]}
                float* aE0 = acc[np * 2];       // rowset0 regs [0..3]
                float* aO0 = acc[np * 2 + 1];
                mma_bf16(aE0,     ahi0, bhi[0], bhi[2]);
                mma_bf16(aE0,     ahi0, blo[0], blo[2]);
                mma_bf16(aE0,     alo0, bhi[0], bhi[2]);
                mma_bf16(aO0,     ahi0, bhi[1], bhi[3]);
                mma_bf16(aO0,     ahi0, blo[1], blo[3]);
                mma_bf16(aO0,     alo0, bhi[1], bhi[3]);
                mma_bf16(aE0 + 4, ahi1, bhi[0], bhi[2]);
                mma_bf16(aE0 + 4, ahi1, blo[0], blo[2]);
                mma_bf16(aE0 + 4, alo1, bhi[0], bhi[2]);
                mma_bf16(aO0 + 4, ahi1, bhi[1], bhi[3]);
                mma_bf16(aO0 + 4, ahi1, blo[1], blo[3]);
                mma_bf16(aO0 + 4, alo1, bhi[1], bhi[3]);
            }
        }

        // --- epilogue: store to g_h0 / g_h1 ---
        int rA = r0 + mrow0 + (lane >> 2);
        float* dst = (nw < 2) ? g_h0 : g_h1;
        int cb = (nw & 1) * 64;
        #pragma unroll
        for (int n = 0; n < 8; n++) {
            int c = cb + n * 8 + ncol;
            if (rA < V)      *(float2*)(dst + (size_t)rA * D + c)        = make_float2(acc[n][0], acc[n][1]);
            if (rA + 8 < V)  *(float2*)(dst + (size_t)(rA + 8) * D + c)  = make_float2(acc[n][2], acc[n][3]);
            if (rA + 16 < V) *(float2*)(dst + (size_t)(rA + 16) * D + c) = make_float2(acc[n][4], acc[n][5]);
            if (rA + 24 < V) *(float2*)(dst + (size_t)(rA + 24) * D + c) = make_float2(acc[n][6], acc[n][7]);
        }
        __syncthreads();   // MMA readers done before next conversion overwrites A
    }
}

// ---------------- aggregation + BN stats ----------------
__global__ void __launch_bounds__(256) agg_kernel(float* __restrict__ stats, int V)
{
    __shared__ float s_sum[D];
    __shared__ float s_sq[D];

    int tid  = threadIdx.x;
    int wid  = tid >> 5;
    int lane = tid & 31;
    int c0   = lane * 4;

    if (tid < D) { s_sum[tid] = 0.f; s_sq[tid] = 0.f; }
    __syncthreads();

    float4 psum = make_float4(0.f, 0.f, 0.f, 0.f);
    float4 psq  = make_float4(0.f, 0.f, 0.f, 0.f);

    int warpStride = gridDim.x * 8;
    for (int v = blockIdx.x * 8 + wid; v < V; v += warpStride) {
        float4 acc = *(const float4*)(g_h0 + (size_t)v * D + c0);
        int n = g_cnt[v];
        const int* ap = g_adj + (size_t)v * CAP;
        int e = 0;
        for (; e + 3 < n; e += 4) {
            int u0 = ap[e], u1 = ap[e + 1], u2 = ap[e + 2], u3 = ap[e + 3];
            float4 t0 = __ldg((const float4*)(g_h1 + (size_t)u0 * D + c0));
            float4 t1 = __ldg((const float4*)(g_h1 + (size_t)u1 * D + c0));
            float4 t2 = __ldg((const float4*)(g_h1 + (size_t)u2 * D + c0));
            float4 t3 = __ldg((const float4*)(g_h1 + (size_t)u3 * D + c0));
            acc.x += (t0.x + t1.x) + (t2.x + t3.x);
            acc.y += (t0.y + t1.y) + (t2.y + t3.y);
            acc.z += (t0.z + t1.z) + (t2.z + t3.z);
            acc.w += (t0.w + t1.w) + (t2.w + t3.w);
        }
        for (; e < n; e++) {
            int u = ap[e];
            float4 t = __ldg((const float4*)(g_h1 + (size_t)u * D + c0));
            acc.x += t.x; acc.y += t.y; acc.z += t.z; acc.w += t.w;
        }
        float dv = g_dinv[v];
        acc.x *= dv; acc.y *= dv; acc.z *= dv; acc.w *= dv;
        *(float4*)(g_y + (size_t)v * D + c0) = acc;

        psum.x += acc.x; psum.y += acc.y; psum.z += acc.z; psum.w += acc.w;
        psq.x  += acc.x * acc.x; psq.y += acc.y * acc.y;
        psq.z  += acc.z * acc.z; psq.w += acc.w * acc.w;
    }

    atomicAdd(&s_sum[c0 + 0], psum.x);
    atomicAdd(&s_sum[c0 + 1], psum.y);
    atomicAdd(&s_sum[c0 + 2], psum.z);
    atomicAdd(&s_sum[c0 + 3], psum.w);
    atomicAdd(&s_sq[c0 + 0],  psq.x);
    atomicAdd(&s_sq[c0 + 1],  psq.y);
    atomicAdd(&s_sq[c0 + 2],  psq.z);
    atomicAdd(&s_sq[c0 + 3],  psq.w);
    __syncthreads();

    if (tid < D) {
        atomicAdd(&stats[tid],     s_sum[tid]);
        atomicAdd(&stats[D + tid], s_sq[tid]);
    }
}

// ---------------- final BN + ReLU + residual -> out ----------------
__global__ void __launch_bounds__(256) norm_final(
    const float* __restrict__ stats,
    const float* __restrict__ gamma, const float* __restrict__ beta,
    const float* __restrict__ res,
    float* __restrict__ out, int V, float invV)
{
    __shared__ float s_scale[D];
    __shared__ float s_shift[D];

    int tid = threadIdx.x;
    if (tid < D) {
        float mu  = stats[tid] * invV;
        float var = stats[D + tid] * invV - mu * mu;
        float rs  = rsqrtf(var + 1e-5f);
        float sc  = gamma[tid] * rs;
        s_scale[tid] = sc;
        s_shift[tid] = beta[tid] - mu * sc;
    }
    __syncthreads();

    int total = V * (D / 4);
    for (int f = blockIdx.x * blockDim.x + tid; f < total; f += gridDim.x * blockDim.x) {
        int c = (f & 31) * 4;
        float4 t = *(const float4*)(g_y + (size_t)f * 4);
        float4 r = *(const float4*)(res + (size_t)f * 4);
        float4 o;
        o.x = fmaxf(fmaf(t.x, s_scale[c + 0], s_shift[c + 0]) + r.x, 0.f);
        o.y = fmaxf(fmaf(t.y, s_scale[c + 1], s_shift[c + 1]) + r.y, 0.f);
        o.z = fmaxf(fmaf(t.z, s_scale[c + 2], s_shift[c + 2]) + r.z, 0.f);
        o.w = fmaxf(fmaf(t.w, s_scale[c + 3], s_shift[c + 3]) + r.w, 0.f);
        *(float4*)(out + (size_t)f * 4) = o;
    }
}

// ---------------- launch ----------------
extern "C" void kernel_launch(void* const* d_in, const int* in_sizes, int n_in,
                              void* d_out, int out_size)
{
    const float* features = (const float*)d_in[0];
    const int*   edges    = (const int*)  d_in[1];
    const float* W0       = (const float*)d_in[2];
    const float* b0       = (const float*)d_in[3];
    const float* W1       = (const float*)d_in[4];
    const float* b1       = (const float*)d_in[5];
    const float* gamma    = (const float*)d_in[6];
    const float* beta     = (const float*)d_in[7];
    float* out = (float*)d_out;

    int V = in_sizes[0] / D;
    int E = in_sizes[1] / 2;
    float invV = 1.0f / (float)V;

    const int SMEM_BYTES = (2 * 256 + 2 * TM_ROWS) * KS * 2;
    cudaFuncSetAttribute(gemm_dual_tc, cudaFuncAttributeMaxDynamicSharedMemorySize, SMEM_BYTES);

    float* statsP = nullptr;
    cudaGetSymbolAddress((void**)&statsP, g_stats);

    zero_kernel<<<(V + 255) / 256, 256>>>(V);
    build_adj<<<(E + 255) / 256, 256>>>(edges, E);
    dinv_kernel<<<(V + 255) / 256, 256>>>(V);

    for (int l = 0; l < 3; l++) {
        const float* gPrev = (l == 0) ? nullptr : gamma + (size_t)(l - 1) * D;
        const float* bPrev = (l == 0) ? nullptr : beta  + (size_t)(l - 1) * D;
        gemm_dual_tc<<<148, TC_THR, SMEM_BYTES>>>(
            features, l,
            W0 + (size_t)l * D * D, b0 + (size_t)l * D,
            W1 + (size_t)l * D * D, b1 + (size_t)l * D,
            gPrev, bPrev, V, invV);

        agg_kernel<<<592, 256>>>(statsP + l * 2 * D, V);
    }

    norm_final<<<592, 256>>>(statsP + 2 * 2 * D,
                             gamma + 2 * (size_t)D, beta + 2 * (size_t)D,
                             features, out, V, invV);
}